// round 9
// baseline (speedup 1.0000x reference)
#include <cuda_runtime.h>
#include <cstdint>

// CapsNet dynamic routing — tf32 mma.sync GEMMs, hi/lo split precomputed at
// smem-store time (inner loop = LDS + MMA only), balanced warp tiles.
// x: [256, 2401, 8] fp32   W: [2401, 8, 16, 8] fp32   out: [256, 8, 16] fp32

#define IN_CAPS 2401
#define BATCH 256
#define KTOT 19208
#define KPADS 19216      // 1201 * 16
#define NROWS 19328      // 302 * 64
#define NOC 128
#define NSPLIT 37

__device__ __align__(16) float g_Xp[(size_t)BATCH * KPADS];
__device__ __align__(16) float g_XT[(size_t)NROWS * BATCH];
__device__ __align__(16) float g_Vt[NOC * BATCH];
__device__ float g_Spart[(size_t)NSPLIT * BATCH * NOC];
__device__ float g_b[IN_CAPS * 8];
__device__ float g_C[IN_CAPS * 8];

// ---------------------------------------------------------------------------
__device__ __forceinline__ float tf32_hi(float x) {
    unsigned r;
    asm("cvt.rna.tf32.f32 %0, %1;" : "=r"(r) : "f"(x));
    return __uint_as_float(r);
}
__device__ __forceinline__ void mma8(float* d, const unsigned* a, unsigned b0, unsigned b1) {
    asm volatile(
        "mma.sync.aligned.m16n8k8.row.col.f32.tf32.tf32.f32 "
        "{%0,%1,%2,%3}, {%4,%5,%6,%7}, {%8,%9}, {%0,%1,%2,%3};"
        : "+f"(d[0]), "+f"(d[1]), "+f"(d[2]), "+f"(d[3])
        : "r"(a[0]), "r"(a[1]), "r"(a[2]), "r"(a[3]), "r"(b0), "r"(b1));
}
__device__ __forceinline__ unsigned ldsu(const float* p) { return __float_as_uint(*p); }

// split a float4 into tf32 hi / residual lo
__device__ __forceinline__ void split4(float4 v, float4& h, float4& l) {
    h.x = tf32_hi(v.x); h.y = tf32_hi(v.y); h.z = tf32_hi(v.z); h.w = tf32_hi(v.w);
    l.x = v.x - h.x;    l.y = v.y - h.y;    l.z = v.z - h.z;    l.w = v.w - h.w;
}

// ---------------------------------------------------------------------------
__global__ void init_kernel() {
    int t = blockIdx.x * blockDim.x + threadIdx.x;
    if (t < IN_CAPS * 8) { g_b[t] = 0.0f; g_C[t] = 0.125f; }
}

// Pad/copy X -> g_Xp and transpose -> g_XT. grid (604, 8) x 256.
__global__ void __launch_bounds__(256) setup_kernel(const float* __restrict__ X) {
    __shared__ float s[32][33];
    int k0 = blockIdx.x * 32, b0 = blockIdx.y * 32;
    int tx = threadIdx.x & 31, ty = threadIdx.x >> 5;
#pragma unroll
    for (int j = 0; j < 4; j++) {
        int b = b0 + ty + j * 8;
        int k = k0 + tx;
        float v = (k < KTOT) ? X[(size_t)b * KTOT + k] : 0.0f;
        s[ty + j * 8][tx] = v;
        if (k < KPADS) g_Xp[(size_t)b * KPADS + k] = v;
    }
    __syncthreads();
#pragma unroll
    for (int j = 0; j < 4; j++) {
        int r = k0 + ty + j * 8;
        int b = b0 + tx;
        g_XT[(size_t)r * BATCH + b] = s[tx][ty + j * 8];
    }
}

// softmax over o for each capsule
__global__ void __launch_bounds__(128) compute_C_kernel() {
    int i = blockIdx.x * 128 + threadIdx.x;
    if (i >= IN_CAPS) return;
    float bv[8];
    float mx = -1e30f;
#pragma unroll
    for (int o = 0; o < 8; o++) { bv[o] = g_b[i * 8 + o]; mx = fmaxf(mx, bv[o]); }
    float sum = 0.0f;
#pragma unroll
    for (int o = 0; o < 8; o++) { bv[o] = expf(bv[o] - mx); sum += bv[o]; }
    float inv = 1.0f / sum;
#pragma unroll
    for (int o = 0; o < 8; o++) g_C[i * 8 + o] = bv[o] * inv;
}

// ---------------------------------------------------------------------------
// S = X @ (C.*W)^T, split-K. grid (8, 37) x 256 thr = 296 CTAs (2/SM exact).
// CTA tile 32 batch x 128 n; warp m16n32 (wm=w&1, wn=w>>1).
__global__ void __launch_bounds__(256) gemm_S_kernel(const float* __restrict__ W) {
    __shared__ __align__(16) float XsH[32 * 20], XsL[32 * 20];
    __shared__ __align__(16) float BsH[128 * 20], BsL[128 * 20];

    int t = threadIdx.x;
    int w = t >> 5, lane = t & 31;
    int wm = w & 1, wn = w >> 1;
    int g = lane >> 2, tig = lane & 3;
    int b0 = blockIdx.x * 32;
    int split = blockIdx.y;
    int cbase = split * 32 + min(split, 17);
    int cnt = 32 + (split < 17 ? 1 : 0);

    float acc[4][4];
#pragma unroll
    for (int j = 0; j < 4; j++)
#pragma unroll
        for (int e = 0; e < 4; e++) acc[j][e] = 0.0f;

    int xrow = (t & 127) >> 2, xk4 = t & 3;   // X loader: t<128 only
    float4 pxv = make_float4(0.f, 0.f, 0.f, 0.f), pbv[2];
    float pcc[2];

    {   // prefetch slab 0
        int k0 = cbase * 16;
        if (t < 128)
            pxv = *reinterpret_cast<const float4*>(g_Xp + (size_t)(b0 + xrow) * KPADS + k0 + xk4 * 4);
#pragma unroll
        for (int p = 0; p < 2; p++) {
            int u = t + p * 256;
            int n = u >> 2, kk4 = u & 3;
            int i = (k0 >> 3) + (kk4 >> 1);
            int o = n >> 4, c = n & 15, d4 = (kk4 & 1) * 4;
            int iw = min(i, IN_CAPS - 1);
            pbv[p] = *reinterpret_cast<const float4*>(W + (size_t)iw * 1024 + o * 128 + c * 8 + d4);
            pcc[p] = (i < IN_CAPS) ? g_C[i * 8 + o] : 0.0f;
        }
    }

    for (int cs = 0; cs < cnt; cs++) {
        __syncthreads();
        if (t < 128) {
            float4 h, l;
            split4(pxv, h, l);
            *reinterpret_cast<float4*>(XsH + xrow * 20 + xk4 * 4) = h;
            *reinterpret_cast<float4*>(XsL + xrow * 20 + xk4 * 4) = l;
        }
#pragma unroll
        for (int p = 0; p < 2; p++) {
            int u = t + p * 256;
            int n = u >> 2, kk4 = u & 3;
            float cc = pcc[p];
            float4 sv = make_float4(cc * pbv[p].x, cc * pbv[p].y, cc * pbv[p].z, cc * pbv[p].w);
            float4 h, l;
            split4(sv, h, l);
            *reinterpret_cast<float4*>(BsH + n * 20 + kk4 * 4) = h;
            *reinterpret_cast<float4*>(BsL + n * 20 + kk4 * 4) = l;
        }
        __syncthreads();

        if (cs + 1 < cnt) {
            int k0 = (cbase + cs + 1) * 16;
            if (t < 128)
                pxv = *reinterpret_cast<const float4*>(g_Xp + (size_t)(b0 + xrow) * KPADS + k0 + xk4 * 4);
#pragma unroll
            for (int p = 0; p < 2; p++) {
                int u = t + p * 256;
                int n = u >> 2, kk4 = u & 3;
                int i = (k0 >> 3) + (kk4 >> 1);
                int o = n >> 4, c = n & 15, d4 = (kk4 & 1) * 4;
                int iw = min(i, IN_CAPS - 1);
                pbv[p] = *reinterpret_cast<const float4*>(W + (size_t)iw * 1024 + o * 128 + c * 8 + d4);
                pcc[p] = (i < IN_CAPS) ? g_C[i * 8 + o] : 0.0f;
            }
        }

#pragma unroll
        for (int s = 0; s < 2; s++) {
            int kb = s * 8;
            int rb = wm * 16;
            unsigned ah[4] = {ldsu(XsH + (rb + g) * 20 + kb + tig),
                              ldsu(XsH + (rb + g + 8) * 20 + kb + tig),
                              ldsu(XsH + (rb + g) * 20 + kb + tig + 4),
                              ldsu(XsH + (rb + g + 8) * 20 + kb + tig + 4)};
            unsigned al[4] = {ldsu(XsL + (rb + g) * 20 + kb + tig),
                              ldsu(XsL + (rb + g + 8) * 20 + kb + tig),
                              ldsu(XsL + (rb + g) * 20 + kb + tig + 4),
                              ldsu(XsL + (rb + g + 8) * 20 + kb + tig + 4)};
#pragma unroll
            for (int j = 0; j < 4; j++) {
                int col = wn * 32 + j * 8 + g;
                unsigned bh0 = ldsu(BsH + col * 20 + kb + tig);
                unsigned bh1 = ldsu(BsH + col * 20 + kb + tig + 4);
                unsigned bl0 = ldsu(BsL + col * 20 + kb + tig);
                unsigned bl1 = ldsu(BsL + col * 20 + kb + tig + 4);
                mma8(acc[j], ah, bh0, bh1);
                mma8(acc[j], ah, bl0, bl1);
                mma8(acc[j], al, bh0, bh1);
            }
        }
    }

    float* dst = g_Spart + ((size_t)split * BATCH + b0 + wm * 16) * NOC + wn * 32;
#pragma unroll
    for (int j = 0; j < 4; j++) {
        int col = j * 8 + 2 * tig;
        *reinterpret_cast<float2*>(dst + g * NOC + col) = make_float2(acc[j][0], acc[j][1]);
        *reinterpret_cast<float2*>(dst + (g + 8) * NOC + col) = make_float2(acc[j][2], acc[j][3]);
    }
}

// ---------------------------------------------------------------------------
// Sum 37 partials + squash. 8 lanes/output, grid 256 x 256 thr.
__global__ void __launch_bounds__(256) reduce_squash_kernel(float* __restrict__ out, int last) {
    int id = blockIdx.x * 256 + threadIdx.x;
    int gg = id >> 3;        // float4 column 0..8191
    int q = id & 7;          // partial lane
    const float4* sp = reinterpret_cast<const float4*>(g_Spart);

    float4 s = make_float4(0.f, 0.f, 0.f, 0.f);
#pragma unroll 5
    for (int p = q; p < NSPLIT; p += 8) {
        float4 v = sp[(size_t)p * (BATCH * NOC / 4) + gg];
        s.x += v.x; s.y += v.y; s.z += v.z; s.w += v.w;
    }
#pragma unroll
    for (int off = 1; off <= 4; off <<= 1) {
        s.x += __shfl_xor_sync(0xffffffffu, s.x, off);
        s.y += __shfl_xor_sync(0xffffffffu, s.y, off);
        s.z += __shfl_xor_sync(0xffffffffu, s.z, off);
        s.w += __shfl_xor_sync(0xffffffffu, s.w, off);
    }
    float msq = s.x * s.x + s.y * s.y + s.z * s.z + s.w * s.w;
    msq += __shfl_xor_sync(0xffffffffu, msq, 8);
    msq += __shfl_xor_sync(0xffffffffu, msq, 16);
    float f = sqrtf(msq) / (1.0f + msq);
    float4 v = make_float4(s.x * f, s.y * f, s.z * f, s.w * f);
    if (q == 0) {
        if (last) {
            reinterpret_cast<float4*>(out)[gg] = v;
        } else {
            float vv[4] = {v.x, v.y, v.z, v.w};
            int b = gg >> 5, n0 = (gg & 31) * 4;
#pragma unroll
            for (int e = 0; e < 4; e++)
                g_Vt[(n0 + e) * BATCH + b] = vv[e];
        }
    }
}

// ---------------------------------------------------------------------------
// Y = XT @ Vt^T (K=256) + agreement epilogue -> g_b. grid 302 x 256 thr.
// CTA 64 rows x 128 cols; warp m32n32 (wm=w&1, wn=w>>1). Ysh unioned over tiles.
__global__ void __launch_bounds__(256) gemm_Ya_kernel(const float* __restrict__ W) {
    __shared__ __align__(16) char pool[64 * 132 * 4];   // 33792 B
    float* XsH = reinterpret_cast<float*>(pool);        // 64*20
    float* XsL = XsH + 1280;                            // 64*20
    float* BsH = XsL + 1280;                            // 128*20
    float* BsL = BsH + 2560;                            // 128*20 (total 30720 B)
    float* Ysh = reinterpret_cast<float*>(pool);        // 64*132 after mainloop

    int t = threadIdx.x;
    int w = t >> 5, lane = t & 31;
    int wm = w & 1, wn = w >> 1;
    int g = lane >> 2, tig = lane & 3;
    int r0 = blockIdx.x * 64;

    float acc[2][4][4];
#pragma unroll
    for (int mt = 0; mt < 2; mt++)
#pragma unroll
        for (int j = 0; j < 4; j++)
#pragma unroll
            for (int e = 0; e < 4; e++) acc[mt][j][e] = 0.0f;

    int xrow = t >> 2, xk4 = t & 3;
    float4 pxv, pbv[2];
    pxv = *reinterpret_cast<const float4*>(g_XT + (size_t)(r0 + xrow) * BATCH + xk4 * 4);
#pragma unroll
    for (int p = 0; p < 2; p++) {
        int u = t + p * 256;
        int n = u >> 2, kk4 = u & 3;
        pbv[p] = *reinterpret_cast<const float4*>(g_Vt + n * BATCH + kk4 * 4);
    }

    for (int cs = 0; cs < 16; cs++) {
        __syncthreads();
        {
            float4 h, l;
            split4(pxv, h, l);
            *reinterpret_cast<float4*>(XsH + xrow * 20 + xk4 * 4) = h;
            *reinterpret_cast<float4*>(XsL + xrow * 20 + xk4 * 4) = l;
        }
#pragma unroll
        for (int p = 0; p < 2; p++) {
            int u = t + p * 256;
            int n = u >> 2, kk4 = u & 3;
            float4 h, l;
            split4(pbv[p], h, l);
            *reinterpret_cast<float4*>(BsH + n * 20 + kk4 * 4) = h;
            *reinterpret_cast<float4*>(BsL + n * 20 + kk4 * 4) = l;
        }
        __syncthreads();

        if (cs + 1 < 16) {
            int k0 = (cs + 1) * 16;
            pxv = *reinterpret_cast<const float4*>(g_XT + (size_t)(r0 + xrow) * BATCH + k0 + xk4 * 4);
#pragma unroll
            for (int p = 0; p < 2; p++) {
                int u = t + p * 256;
                int n = u >> 2, kk4 = u & 3;
                pbv[p] = *reinterpret_cast<const float4*>(g_Vt + n * BATCH + k0 + kk4 * 4);
            }
        }

#pragma unroll
        for (int s = 0; s < 2; s++) {
            int kb = s * 8;
            unsigned ah[2][4], al[2][4];
#pragma unroll
            for (int mt = 0; mt < 2; mt++) {
                int rb = wm * 32 + mt * 16;
                ah[mt][0] = ldsu(XsH + (rb + g) * 20 + kb + tig);
                ah[mt][1] = ldsu(XsH + (rb + g + 8) * 20 + kb + tig);
                ah[mt][2] = ldsu(XsH + (rb + g) * 20 + kb + tig + 4);
                ah[mt][3] = ldsu(XsH + (rb + g + 8) * 20 + kb + tig + 4);
                al[mt][0] = ldsu(XsL + (rb + g) * 20 + kb + tig);
                al[mt][1] = ldsu(XsL + (rb + g + 8) * 20 + kb + tig);
                al[mt][2] = ldsu(XsL + (rb + g) * 20 + kb + tig + 4);
                al[mt][3] = ldsu(XsL + (rb + g + 8) * 20 + kb + tig + 4);
            }
#pragma unroll
            for (int j = 0; j < 4; j++) {
                int col = wn * 32 + j * 8 + g;
                unsigned bh0 = ldsu(BsH + col * 20 + kb + tig);
                unsigned bh1 = ldsu(BsH + col * 20 + kb + tig + 4);
                unsigned bl0 = ldsu(BsL + col * 20 + kb + tig);
                unsigned bl1 = ldsu(BsL + col * 20 + kb + tig + 4);
#pragma unroll
                for (int mt = 0; mt < 2; mt++) {
                    mma8(acc[mt][j], ah[mt], bh0, bh1);
                    mma8(acc[mt][j], ah[mt], bl0, bl1);
                    mma8(acc[mt][j], al[mt], bh0, bh1);
                }
            }
        }
    }

    // Stage Y tile (pool reused — all tile reads are done), then agreement.
    __syncthreads();
#pragma unroll
    for (int mt = 0; mt < 2; mt++)
#pragma unroll
        for (int j = 0; j < 4; j++) {
            int col = wn * 32 + j * 8 + 2 * tig;
            int row = wm * 32 + mt * 16 + g;
            *reinterpret_cast<float2*>(&Ysh[row * 132 + col]) =
                make_float2(acc[mt][j][0], acc[mt][j][1]);
            *reinterpret_cast<float2*>(&Ysh[(row + 8) * 132 + col]) =
                make_float2(acc[mt][j][2], acc[mt][j][3]);
        }
    __syncthreads();

    // a[i,o] = (1/B) sum_{c,d} W[i,o,c,d] * Y[(i,d),(o,c)] ; b += a
    if (t < 64) {
        int il = t >> 3;
        int o = t & 7;
        int i = r0 / 8 + il;
        if (i < IN_CAPS) {
            const float4* w4 = reinterpret_cast<const float4*>(W + (size_t)i * 1024 + o * 128);
            float sum = 0.0f;
#pragma unroll
            for (int c = 0; c < 16; c++) {
                float4 wa = w4[c * 2];
                float4 wb = w4[c * 2 + 1];
                int col = o * 16 + c;
                int rb = il * 8;
                sum += wa.x * Ysh[(rb + 0) * 132 + col] + wa.y * Ysh[(rb + 1) * 132 + col] +
                       wa.z * Ysh[(rb + 2) * 132 + col] + wa.w * Ysh[(rb + 3) * 132 + col] +
                       wb.x * Ysh[(rb + 4) * 132 + col] + wb.y * Ysh[(rb + 5) * 132 + col] +
                       wb.z * Ysh[(rb + 6) * 132 + col] + wb.w * Ysh[(rb + 7) * 132 + col];
            }
            g_b[i * 8 + o] += sum * (1.0f / 256.0f);
        }
    }
}

// ---------------------------------------------------------------------------
extern "C" void kernel_launch(void* const* d_in, const int* in_sizes, int n_in,
                              void* d_out, int out_size) {
    const float* x;
    const float* W;
    if (in_sizes[0] == BATCH * KTOT) {
        x = (const float*)d_in[0];
        W = (const float*)d_in[1];
    } else {
        x = (const float*)d_in[1];
        W = (const float*)d_in[0];
    }
    float* out = (float*)d_out;

    init_kernel<<<76, 256>>>();
    setup_kernel<<<dim3(604, 8), 256>>>(x);

    for (int it = 0; it < 3; it++) {
        gemm_S_kernel<<<dim3(8, NSPLIT), 256>>>(W);
        reduce_squash_kernel<<<256, 256>>>(out, it == 2 ? 1 : 0);
        if (it < 2) {
            gemm_Ya_kernel<<<302, 256>>>(W);
            compute_C_kernel<<<19, 128>>>();
        }
    }
}

// round 10
// speedup vs baseline: 1.2993x; 1.2993x over previous
#include <cuda_runtime.h>

// CapsNet dynamic routing, FFMA2 GEMMs. R10: crossbar fix — x-fragment reads
// vectorized (2x LDS.128 + packs instead of 8 scalar LDS), halving smem
// crossbar demand per warp-kk (12 -> 6 cyc vs 64 FFMA2 cyc).
// x: [256, 2401, 8] fp32   W: [2401, 8, 16, 8] fp32   out: [256, 8, 16] fp32

#define IN_CAPS 2401
#define BATCH 256
#define KTOT 19208                 // 2401*8
#define NOC 128                    // 8*16
#define NSPLIT 73
#define CHUNK 264                  // 72*264 + 200 = 19208, multiples of 8

typedef unsigned long long ull;

__device__ float g_Spart[(size_t)NSPLIT * BATCH * NOC];  // 9.57 MB
__device__ float g_V[BATCH * NOC];
__device__ float g_b[IN_CAPS * 8];
__device__ float g_bp[2][IN_CAPS * 8];
__device__ float g_C[IN_CAPS * 8];

__device__ __forceinline__ void ffma2(ull& acc, ull a, ull b) {
    asm("fma.rn.f32x2 %0, %1, %2, %0;" : "+l"(acc) : "l"(a), "l"(b));
}
__device__ __forceinline__ ull pack2(float x) {
    ull r;
    unsigned u = __float_as_uint(x);
    asm("mov.b64 %0, {%1, %1};" : "=l"(r) : "r"(u));
    return r;
}

// ---------------------------------------------------------------------------
__global__ void init_kernel() {
    int t = blockIdx.x * blockDim.x + threadIdx.x;
    if (t < IN_CAPS * 8) { g_b[t] = 0.0f; g_C[t] = 0.125f; }
}

// b += a (both K-split partials), softmax over o -> C
__global__ void __launch_bounds__(128) compute_C_kernel() {
    int i = blockIdx.x * 128 + threadIdx.x;
    if (i >= IN_CAPS) return;
    float bv[8];
#pragma unroll
    for (int o = 0; o < 8; o++) {
        bv[o] = g_b[i * 8 + o] + g_bp[0][i * 8 + o] + g_bp[1][i * 8 + o];
        g_b[i * 8 + o] = bv[o];
    }
    float mx = -1e30f;
#pragma unroll
    for (int o = 0; o < 8; o++) mx = fmaxf(mx, bv[o]);
    float sum = 0.0f;
#pragma unroll
    for (int o = 0; o < 8; o++) { bv[o] = expf(bv[o] - mx); sum += bv[o]; }
    float inv = 1.0f / sum;
#pragma unroll
    for (int o = 0; o < 8; o++) g_C[i * 8 + o] = bv[o] * inv;
}

// ---------------------------------------------------------------------------
// S = X @ (C .* W), split-K partials. grid (2, 73) x 256 thr.
// CTA tile 128 batch x 128 cols, per-thread 8x8, prefetched slabs.
__global__ void __launch_bounds__(256, 2) gemm_S_kernel(const float* __restrict__ X,
                                                        const float* __restrict__ W) {
    __shared__ __align__(16) float Xs[8][132];
    __shared__ __align__(16) float Ms[8][132];

    int b0 = blockIdx.x * 128;
    int kstart = blockIdx.y * CHUNK;
    int kend = min(kstart + CHUNK, KTOT);
    int t = threadIdx.x;
    int tx = t & 15, ty = t >> 4;

    ull acc[8][4];
#pragma unroll
    for (int r = 0; r < 8; r++)
#pragma unroll
        for (int j = 0; j < 4; j++) acc[r][j] = 0ull;

    int xbb = t >> 1, xkp = (t & 1) * 4;
    int wl = t * 4;
    int wo = wl >> 7, wc = (wl >> 3) & 15, wd = wl & 7;
    int wcol = wo * 16 + wc;

    // prefetch slab 0
    float4 xv = *reinterpret_cast<const float4*>(X + (size_t)(b0 + xbb) * KTOT + kstart + xkp);
    float4 wv = *reinterpret_cast<const float4*>(W + (size_t)(kstart >> 3) * 1024 + wl);
    float cc = g_C[(kstart >> 3) * 8 + wo];

    for (int k0 = kstart; k0 < kend; k0 += 8) {
        __syncthreads();
        Xs[xkp + 0][xbb] = xv.x; Xs[xkp + 1][xbb] = xv.y;
        Xs[xkp + 2][xbb] = xv.z; Xs[xkp + 3][xbb] = xv.w;
        Ms[wd + 0][wcol] = cc * wv.x; Ms[wd + 1][wcol] = cc * wv.y;
        Ms[wd + 2][wcol] = cc * wv.z; Ms[wd + 3][wcol] = cc * wv.w;
        __syncthreads();

        int kn = k0 + 8;
        if (kn < kend) {  // prefetch next slab
            xv = *reinterpret_cast<const float4*>(X + (size_t)(b0 + xbb) * KTOT + kn + xkp);
            wv = *reinterpret_cast<const float4*>(W + (size_t)(kn >> 3) * 1024 + wl);
            cc = g_C[(kn >> 3) * 8 + wo];
        }

#pragma unroll
        for (int kk = 0; kk < 8; kk++) {
            ull mv[4];
#pragma unroll
            for (int jj = 0; jj < 4; jj++)
                mv[jj] = *reinterpret_cast<const ull*>(&Ms[kk][jj * 32 + tx * 2]);
            float4 xa = *reinterpret_cast<const float4*>(&Xs[kk][ty * 8]);
            float4 xb = *reinterpret_cast<const float4*>(&Xs[kk][ty * 8 + 4]);
            float xr[8] = {xa.x, xa.y, xa.z, xa.w, xb.x, xb.y, xb.z, xb.w};
#pragma unroll
            for (int rr = 0; rr < 8; rr++) {
                ull a = pack2(xr[rr]);
#pragma unroll
                for (int jj = 0; jj < 4; jj++) ffma2(acc[rr][jj], a, mv[jj]);
            }
        }
    }

    float* out = g_Spart + (size_t)blockIdx.y * (BATCH * NOC);
#pragma unroll
    for (int rr = 0; rr < 8; rr++) {
        int bb = b0 + ty * 8 + rr;
#pragma unroll
        for (int jj = 0; jj < 4; jj++)
            *reinterpret_cast<float2*>(out + (size_t)bb * NOC + jj * 32 + tx * 2) =
                *reinterpret_cast<float2*>(&acc[rr][jj]);
    }
}

// ---------------------------------------------------------------------------
// Sum 73 partials + squash. float4, 8 partial-lanes, grid 256 x 256 thr.
__global__ void __launch_bounds__(256) reduce_squash_kernel(float* __restrict__ out, int last) {
    int id = blockIdx.x * 256 + threadIdx.x;
    int gg = id >> 3;        // float4 column 0..8191
    int q = id & 7;          // partial lane
    const float4* sp = reinterpret_cast<const float4*>(g_Spart);

    float4 s = make_float4(0.f, 0.f, 0.f, 0.f);
#pragma unroll 5
    for (int p = q; p < NSPLIT; p += 8) {
        float4 v = sp[(size_t)p * (BATCH * NOC / 4) + gg];
        s.x += v.x; s.y += v.y; s.z += v.z; s.w += v.w;
    }
#pragma unroll
    for (int off = 1; off <= 4; off <<= 1) {
        s.x += __shfl_xor_sync(0xffffffffu, s.x, off);
        s.y += __shfl_xor_sync(0xffffffffu, s.y, off);
        s.z += __shfl_xor_sync(0xffffffffu, s.z, off);
        s.w += __shfl_xor_sync(0xffffffffu, s.w, off);
    }
    float msq = s.x * s.x + s.y * s.y + s.z * s.z + s.w * s.w;
    msq += __shfl_xor_sync(0xffffffffu, msq, 8);
    msq += __shfl_xor_sync(0xffffffffu, msq, 16);
    float f = sqrtf(msq) / (1.0f + msq);
    float4 v = make_float4(s.x * f, s.y * f, s.z * f, s.w * f);
    if (q == 0) {
        reinterpret_cast<float4*>(g_V)[gg] = v;
        if (last) reinterpret_cast<float4*>(out)[gg] = v;
    }
}

// ---------------------------------------------------------------------------
// Y = X^T @ V, K-split 2 over batch, fused agreement into g_bp[split].
// grid (301, 2) x 128 thr, occ 4. CTA tile 64 K-rows x 128 cols, per-thread 8x8.
__global__ void __launch_bounds__(128, 4) gemm_Ya_kernel(const float* __restrict__ X,
                                                         const float* __restrict__ W) {
    __shared__ __align__(16) float Xts[8][68];
    __shared__ __align__(16) float Vs[8][132];

    int r0 = blockIdx.x * 64;
    int split = blockIdx.y;
    int kbeg = split * 128, kfin = kbeg + 128;
    int t = threadIdx.x;
    int tx = t & 15, ty = t >> 4;

    ull acc[8][4];
#pragma unroll
    for (int r = 0; r < 8; r++)
#pragma unroll
        for (int j = 0; j < 4; j++) acc[r][j] = 0ull;

    int lkk = t >> 4;            // 0..7
    int lq = (t & 15) * 4;       // 0..60
    bool xok = (r0 + lq) < KTOT;

    float4 xv = xok ? *reinterpret_cast<const float4*>(X + (size_t)(kbeg + lkk) * KTOT + r0 + lq)
                    : make_float4(0.f, 0.f, 0.f, 0.f);
    float4 va = *reinterpret_cast<const float4*>(g_V + (kbeg + lkk) * NOC + lq);
    float4 vb = *reinterpret_cast<const float4*>(g_V + (kbeg + lkk) * NOC + lq + 64);

    for (int k0 = kbeg; k0 < kfin; k0 += 8) {
        __syncthreads();
        *reinterpret_cast<float4*>(&Xts[lkk][lq]) = xv;
        *reinterpret_cast<float4*>(&Vs[lkk][lq]) = va;
        *reinterpret_cast<float4*>(&Vs[lkk][lq + 64]) = vb;
        __syncthreads();

        int kn = k0 + 8;
        if (kn < kfin) {
            xv = xok ? *reinterpret_cast<const float4*>(X + (size_t)(kn + lkk) * KTOT + r0 + lq)
                     : make_float4(0.f, 0.f, 0.f, 0.f);
            va = *reinterpret_cast<const float4*>(g_V + (kn + lkk) * NOC + lq);
            vb = *reinterpret_cast<const float4*>(g_V + (kn + lkk) * NOC + lq + 64);
        }

#pragma unroll
        for (int kk = 0; kk < 8; kk++) {
            ull mv[4];
#pragma unroll
            for (int jj = 0; jj < 4; jj++)
                mv[jj] = *reinterpret_cast<const ull*>(&Vs[kk][jj * 32 + tx * 2]);
            float4 xa = *reinterpret_cast<const float4*>(&Xts[kk][ty * 8]);
            float4 xb = *reinterpret_cast<const float4*>(&Xts[kk][ty * 8 + 4]);
            float xr[8] = {xa.x, xa.y, xa.z, xa.w, xb.x, xb.y, xb.z, xb.w};
#pragma unroll
            for (int rr = 0; rr < 8; rr++) {
                ull a = pack2(xr[rr]);
#pragma unroll
                for (int jj = 0; jj < 4; jj++) ffma2(acc[rr][jj], a, mv[jj]);
            }
        }
    }

    // Agreement partial: a[i,o] = (1/B) sum_{c,d,k in half} W * Y
    int i = r0 / 8 + ty;
    int iw = min(i, IN_CAPS - 1);
    int ohi = tx >> 3;
    int c = (tx & 7) * 2;
    float s[4];
#pragma unroll
    for (int jj = 0; jj < 4; jj++) {
        int oo = jj * 2 + ohi;
        const float4* wp = reinterpret_cast<const float4*>(W + (size_t)iw * 1024 + oo * 128 + c * 8);
        float4 w0 = wp[0], w1 = wp[1], w2 = wp[2], w3 = wp[3];
        float wlo[8] = {w0.x, w0.y, w0.z, w0.w, w1.x, w1.y, w1.z, w1.w};
        float whi[8] = {w2.x, w2.y, w2.z, w2.w, w3.x, w3.y, w3.z, w3.w};
        float sum = 0.0f;
#pragma unroll
        for (int d = 0; d < 8; d++) {
            float2 y = *reinterpret_cast<float2*>(&acc[d][jj]);
            sum += wlo[d] * y.x + whi[d] * y.y;
        }
        s[jj] = sum;
    }
#pragma unroll
    for (int jj = 0; jj < 4; jj++) {
        s[jj] += __shfl_xor_sync(0xffffffffu, s[jj], 1);
        s[jj] += __shfl_xor_sync(0xffffffffu, s[jj], 2);
        s[jj] += __shfl_xor_sync(0xffffffffu, s[jj], 4);
    }
    if ((tx & 7) == 0 && i < IN_CAPS) {
#pragma unroll
        for (int jj = 0; jj < 4; jj++)
            g_bp[split][i * 8 + jj * 2 + ohi] = s[jj] * (1.0f / 256.0f);
    }
}

// ---------------------------------------------------------------------------
extern "C" void kernel_launch(void* const* d_in, const int* in_sizes, int n_in,
                              void* d_out, int out_size) {
    const float* x;
    const float* W;
    if (in_sizes[0] == BATCH * KTOT) {
        x = (const float*)d_in[0];
        W = (const float*)d_in[1];
    } else {
        x = (const float*)d_in[1];
        W = (const float*)d_in[0];
    }
    float* out = (float*)d_out;

    init_kernel<<<76, 256>>>();

    for (int it = 0; it < 3; it++) {
        gemm_S_kernel<<<dim3(2, NSPLIT), 256>>>(x, W);
        reduce_squash_kernel<<<256, 256>>>(out, it == 2 ? 1 : 0);
        if (it < 2) {
            gemm_Ya_kernel<<<dim3(301, 2), 128>>>(x, W);
            compute_C_kernel<<<19, 128>>>();
        }
    }
}